// round 1
// baseline (speedup 1.0000x reference)
#include <cuda_runtime.h>
#include <cuda_bf16.h>
#include <math_constants.h>

// VectorQuantizer: N=32768 rows (16*2048), D=256, K=4096 codewords.
// dist[r,k] = fl( fl(A_r + B_k) - fl(2 * dot_fma_seq(x_r, c_k)) )
//   A_r = sequential fp32 sum of fl(x_i^2), ascending i
//   B_k = sequential fp32 sum of fl(c_i^2), ascending i
//   dot = single-accumulator ascending-k fp32 FMA chain (Eigen gebp / cuBLAS SGEMM order)
// argmin with first-occurrence (lowest index) tie-break.
// out = fl(x + fl(q - x));  loss = fl(fl(m*0.25) + m), m = mean(fl(q-x)^2).

#define VQ_N 32768
#define VQ_D 256
#define VQ_K 4096

#define TM 128   // rows per block tile
#define TN 128   // codewords per k-tile
#define TD 32    // depth chunk

__device__ float  g_A[VQ_N];
__device__ float  g_B[VQ_K];
__device__ int    g_ind[VQ_N];
__device__ double g_losssum;

// ---------------------------------------------------------------- zero loss
__global__ void vq_zero_kernel() { g_losssum = 0.0; }

// ---------------------------------------------------------------- ||c_k||^2
__global__ void vq_cbnorm_kernel(const float* __restrict__ cb) {
    int k = blockIdx.x * blockDim.x + threadIdx.x;
    if (k >= VQ_K) return;
    const float* c = cb + (size_t)k * VQ_D;
    float s = 0.0f;
    for (int i = 0; i < VQ_D; i++) {
        float v = c[i];
        float t = __fmul_rn(v, v);
        s = __fadd_rn(s, t);   // strict sequential ascending order
    }
    g_B[k] = s;
}

// ---------------------------------------------------------------- ||x_r||^2
__global__ void vq_rowsum_kernel(const float* __restrict__ x) {
    int r = blockIdx.x * blockDim.x + threadIdx.x;
    if (r >= VQ_N) return;
    const float* xr = x + (size_t)r * VQ_D;
    float s = 0.0f;
    for (int i = 0; i < VQ_D; i++) {
        float v = xr[i];
        float t = __fmul_rn(v, v);
        s = __fadd_rn(s, t);   // strict sequential ascending order
    }
    g_A[r] = s;
}

// ---------------------------------------------------------------- main GEMM + argmin
// 256 threads, 16x16 logical grid, 8x8 register tile per thread.
__global__ __launch_bounds__(256, 2) void vq_argmin_kernel(
    const float* __restrict__ x, const float* __restrict__ cb)
{
    __shared__ float xs[TD][TM + 4];   // transposed: xs[i][row_local], pitch 132 words
    __shared__ float cs[TD][TN + 4];   // transposed: cs[i][k_local]

    const int tid = threadIdx.x;
    const int tx = tid & 15;           // k-group  (8 contiguous k's)
    const int ty = tid >> 4;           // row-group (8 contiguous rows)
    const int row0 = blockIdx.x * TM;

    float Ar[8];
#pragma unroll
    for (int a = 0; a < 8; a++) Ar[a] = g_A[row0 + ty * 8 + a];

    float bv[8];
    int   bi[8];
#pragma unroll
    for (int a = 0; a < 8; a++) { bv[a] = CUDART_INF_F; bi[a] = 0; }

    for (int k0 = 0; k0 < VQ_K; k0 += TN) {
        float acc[8][8];
#pragma unroll
        for (int a = 0; a < 8; a++)
#pragma unroll
            for (int b = 0; b < 8; b++) acc[a][b] = 0.0f;

        for (int d0 = 0; d0 < VQ_D; d0 += TD) {
            // cooperative load of x-chunk [TM x TD] and c-chunk [TN x TD], transposed
#pragma unroll
            for (int it = 0; it < 4; it++) {
                int idx = tid + it * 256;       // 0..1023
                int r   = idx >> 3;             // 0..127
                int c4  = (idx & 7) * 4;        // 0,4,...,28
                float4 vx = *(const float4*)(x  + (size_t)(row0 + r) * VQ_D + d0 + c4);
                xs[c4 + 0][r] = vx.x; xs[c4 + 1][r] = vx.y;
                xs[c4 + 2][r] = vx.z; xs[c4 + 3][r] = vx.w;
                float4 vc = *(const float4*)(cb + (size_t)(k0 + r) * VQ_D + d0 + c4);
                cs[c4 + 0][r] = vc.x; cs[c4 + 1][r] = vc.y;
                cs[c4 + 2][r] = vc.z; cs[c4 + 3][r] = vc.w;
            }
            __syncthreads();

#pragma unroll
            for (int i = 0; i < TD; i++) {
                float xv[8], cv[8];
                *(float4*)&xv[0] = *(const float4*)&xs[i][ty * 8];
                *(float4*)&xv[4] = *(const float4*)&xs[i][ty * 8 + 4];
                *(float4*)&cv[0] = *(const float4*)&cs[i][tx * 8];
                *(float4*)&cv[4] = *(const float4*)&cs[i][tx * 8 + 4];
#pragma unroll
                for (int a = 0; a < 8; a++)
#pragma unroll
                    for (int b = 0; b < 8; b++)
                        acc[a][b] = __fmaf_rn(xv[a], cv[b], acc[a][b]);
            }
            __syncthreads();
        }

        // epilogue: dist + running argmin (per-thread k ascending -> strict < keeps lowest)
#pragma unroll
        for (int b = 0; b < 8; b++) {
            int k = k0 + tx * 8 + b;
            float Bk = g_B[k];
#pragma unroll
            for (int a = 0; a < 8; a++) {
                float t    = __fadd_rn(Ar[a], Bk);
                float m2   = __fmul_rn(2.0f, acc[a][b]);
                float dist = __fsub_rn(t, m2);
                if (dist < bv[a]) { bv[a] = dist; bi[a] = k; }
            }
        }
    }

    // cross-thread (tx) reduction with lexicographic (value, index) tie-break
    __syncthreads();
    float* redv = &xs[0][0];           // 128*16 floats = 2048 <= 32*132
    int*   redi = (int*)&cs[0][0];
#pragma unroll
    for (int a = 0; a < 8; a++) {
        int r = ty * 8 + a;
        redv[r * 16 + tx] = bv[a];
        redi[r * 16 + tx] = bi[a];
    }
    __syncthreads();
    if (tid < TM) {
        float best  = redv[tid * 16];
        int   besti = redi[tid * 16];
        for (int t = 1; t < 16; t++) {
            float v = redv[tid * 16 + t];
            int   i2 = redi[tid * 16 + t];
            if (v < best || (v == best && i2 < besti)) { best = v; besti = i2; }
        }
        g_ind[row0 + tid] = besti;
    }
}

// ---------------------------------------------------------------- output + loss accum
__global__ void vq_output_kernel(const float* __restrict__ x,
                                 const float* __restrict__ cb,
                                 float* __restrict__ out)
{
    __shared__ double sd[256];
    int e4 = blockIdx.x * blockDim.x + threadIdx.x;   // one float4 per thread
    double ls = 0.0;
    if (e4 < VQ_N * VQ_D / 4) {
        int base = e4 * 4;
        int row  = base >> 8;
        int col  = base & 255;
        int ind  = g_ind[row];
        float4 xv = *(const float4*)(x  + base);
        float4 qv = *(const float4*)(cb + (size_t)ind * VQ_D + col);
        float d0 = __fsub_rn(qv.x, xv.x);
        float d1 = __fsub_rn(qv.y, xv.y);
        float d2 = __fsub_rn(qv.z, xv.z);
        float d3 = __fsub_rn(qv.w, xv.w);
        float4 ov;
        ov.x = __fadd_rn(xv.x, d0);
        ov.y = __fadd_rn(xv.y, d1);
        ov.z = __fadd_rn(xv.z, d2);
        ov.w = __fadd_rn(xv.w, d3);
        *(float4*)(out + base) = ov;
        ls = (double)__fmul_rn(d0, d0) + (double)__fmul_rn(d1, d1)
           + (double)__fmul_rn(d2, d2) + (double)__fmul_rn(d3, d3);
    }
    sd[threadIdx.x] = ls;
    __syncthreads();
    for (int s = 128; s > 0; s >>= 1) {
        if (threadIdx.x < s) sd[threadIdx.x] += sd[threadIdx.x + s];
        __syncthreads();
    }
    if (threadIdx.x == 0) atomicAdd(&g_losssum, sd[0]);
}

// ---------------------------------------------------------------- finalize loss
__global__ void vq_finalize_kernel(float* __restrict__ out, int has_loss) {
    if (!has_loss) return;
    float m = (float)(g_losssum * (1.0 / (double)(VQ_N * VQ_D)));
    float commit = __fmul_rn(m, 0.25f);
    out[VQ_N * VQ_D] = __fadd_rn(commit, m);
}

// ---------------------------------------------------------------- launch
extern "C" void kernel_launch(void* const* d_in, const int* in_sizes, int n_in,
                              void* d_out, int out_size)
{
    const float* latents  = (const float*)d_in[0];
    const float* codebook = (const float*)d_in[1];
    if (n_in >= 2 && in_sizes[0] == VQ_K * VQ_D && in_sizes[1] == VQ_N * VQ_D) {
        latents  = (const float*)d_in[1];
        codebook = (const float*)d_in[0];
    }
    float* out = (float*)d_out;
    int has_loss = (out_size > VQ_N * VQ_D) ? 1 : 0;

    vq_zero_kernel<<<1, 1>>>();
    vq_cbnorm_kernel<<<VQ_K / 256, 256>>>(codebook);
    vq_rowsum_kernel<<<VQ_N / 256, 256>>>(latents);
    vq_argmin_kernel<<<VQ_N / TM, 256>>>(latents, codebook);
    vq_output_kernel<<<(VQ_N * VQ_D / 4) / 256, 256>>>(latents, codebook, out);
    vq_finalize_kernel<<<1, 1>>>(out, has_loss);
}